// round 15
// baseline (speedup 1.0000x reference)
#include <cuda_runtime.h>
#include <cuda_fp16.h>

#define N_NODES 100000
#define N_EDGES 1600000
#define HID 128

typedef unsigned long long u64;

// Scratch (__device__ globals per allocation rules; zero-initialized at load).
// INVARIANT: g_aggh is all-zero at every kernel_launch entry — statically
// zeroed before the first call, and final_kernel re-zeroes it after reading
// on every call (each thread exclusively owns its 2 nodes).
__device__ uint2  g_xh[N_NODES];   // {f16x2(x0,x1), f16x2(x2,1)} — scatter src
__device__ uint2  g_aggh[N_NODES]; // fp16x2 accumulators {sum01, sum2_deg}
__device__ float4 g_w1[HID];       // (B0,B1,B2,C): B = W_lift@W_rel, C = b_lift@W_rel
__device__ float4 g_w2[HID];       // (A0,A1,A2,D): A = W_lift@W_root, D = b_lift@W_root + b_rel
__device__ float  g_wp[HID];       // W_proj

__device__ __forceinline__ u64 pk(float lo, float hi) {
    u64 r; asm("mov.b64 %0, {%1, %2};" : "=l"(r) : "f"(lo), "f"(hi)); return r;
}
__device__ __forceinline__ u64 pk1(float v) { return pk(v, v); }
#define FMA2(d, a, b, c) asm("fma.rn.f32x2 %0, %1, %2, %3;" : "=l"(d) : "l"(a), "l"(b), "l"(c))
#define UNPK(lo, hi, v)  asm("mov.b64 {%0, %1}, %2;" : "=f"(lo), "=f"(hi) : "l"(v))
#define REDH(ap, u) \
    asm volatile("red.global.add.noftz.v2.f16x2 [%0], {%1,%2};" \
                 :: "l"(ap), "r"((u).x), "r"((u).y) : "memory")
#define GDC_WAIT() asm volatile("griddepcontrol.wait;" ::: "memory")

// ---------------------------------------------------------------------------
// Kernel 1: pack x into f16x2 pairs for the scatter (800KB total)
// ---------------------------------------------------------------------------
__global__ void pack_kernel(const float* __restrict__ x) {
    int n = blockIdx.x * blockDim.x + threadIdx.x;
    if (n >= N_NODES) return;
    float x0 = x[3 * n], x1 = x[3 * n + 1], x2 = x[3 * n + 2];
    __half2 h01 = __floats2half2_rn(x0, x1);
    __half2 h21 = __floats2half2_rn(x2, 1.0f);
    g_xh[n] = make_uint2(*(unsigned*)&h01, *(unsigned*)&h21);
}

// ---------------------------------------------------------------------------
// Kernel 2 (PDL secondary of pack):
//   block 0  = weight fold — no dependency on pack, runs entirely pre-wait
//   blocks 1.. = fp16x2 scatter-add, 8 edges/thread; index loads pre-wait
// ---------------------------------------------------------------------------
__global__ void __launch_bounds__(256)
scatter_kernel(const int* __restrict__ ei,
               const float* __restrict__ W_lift,
               const float* __restrict__ b_lift,
               const float* __restrict__ W_rel,
               const float* __restrict__ b_rel,
               const float* __restrict__ W_root,
               const float* __restrict__ W_proj) {
    if (blockIdx.x == 0) {
        // ---- weight fold: reads only kernel args (independent of pack) ----
        __shared__ float red[2][8][HID];  // 8KB
        int f = threadIdx.x & 127;
        int g = threadIdx.x >> 7;  // 0 or 1
        float b0 = 0.f, b1 = 0.f, b2 = 0.f, c = 0.f;
        float a0 = 0.f, a1 = 0.f, a2 = 0.f, d = 0.f;
        int k0 = g * 64;
#pragma unroll 16
        for (int i = 0; i < 64; i++) {
            int k = k0 + i;
            float wr = W_rel[k * HID + f];
            float wo = W_root[k * HID + f];
            float l0 = W_lift[0 * HID + k];
            float l1 = W_lift[1 * HID + k];
            float l2 = W_lift[2 * HID + k];
            float bl = b_lift[k];
            b0 += l0 * wr; b1 += l1 * wr; b2 += l2 * wr; c += bl * wr;
            a0 += l0 * wo; a1 += l1 * wo; a2 += l2 * wo; d += bl * wo;
        }
        red[g][0][f] = b0; red[g][1][f] = b1; red[g][2][f] = b2; red[g][3][f] = c;
        red[g][4][f] = a0; red[g][5][f] = a1; red[g][6][f] = a2; red[g][7][f] = d;
        __syncthreads();
        if (g == 0) {
            float s[8];
#pragma unroll
            for (int ch = 0; ch < 8; ch++) s[ch] = red[0][ch][f] + red[1][ch][f];
            g_w1[f] = make_float4(s[0], s[1], s[2], s[3]);
            g_w2[f] = make_float4(s[4], s[5], s[6], s[7] + b_rel[f]);
            g_wp[f] = W_proj[f];
        }
        return;
    }

    // ---- scatter: 8 edges per thread, fp16x2 payload (8B gather + 8B red) --
    int t = (blockIdx.x - 1) * 256 + threadIdx.x;
    int e0 = t * 8;
    if (e0 >= N_EDGES) return;
    int4 sa = *(const int4*)(ei + e0);            // pre-wait: harness input
    int4 sb = *(const int4*)(ei + e0 + 4);
    int4 da = *(const int4*)(ei + N_EDGES + e0);
    int4 db = *(const int4*)(ei + N_EDGES + e0 + 4);

    GDC_WAIT();  // pack's g_xh writes must be visible past this point

    // all 8 gathers in flight before any red
    uint2 v0 = __ldg(&g_xh[(unsigned)sa.x]);
    uint2 v1 = __ldg(&g_xh[(unsigned)sa.y]);
    uint2 v2 = __ldg(&g_xh[(unsigned)sa.z]);
    uint2 v3 = __ldg(&g_xh[(unsigned)sa.w]);
    uint2 v4 = __ldg(&g_xh[(unsigned)sb.x]);
    uint2 v5 = __ldg(&g_xh[(unsigned)sb.y]);
    uint2 v6 = __ldg(&g_xh[(unsigned)sb.z]);
    uint2 v7 = __ldg(&g_xh[(unsigned)sb.w]);

    REDH(&g_aggh[(unsigned)da.x], v0);
    REDH(&g_aggh[(unsigned)da.y], v1);
    REDH(&g_aggh[(unsigned)da.z], v2);
    REDH(&g_aggh[(unsigned)da.w], v3);
    REDH(&g_aggh[(unsigned)db.x], v4);
    REDH(&g_aggh[(unsigned)db.y], v5);
    REDH(&g_aggh[(unsigned)db.z], v6);
    REDH(&g_aggh[(unsigned)db.w], v7);
}

// ---------------------------------------------------------------------------
// Kernel 3 (PDL secondary of scatter):
//   out[n] = sum_f tanh(dot(agg,w1_f)+dot(x,1,w2_f)) * wp_f + b_proj
// Root-term x read DIRECTLY from the input (coalesced float2 loads).
// agg read from fp16x2 accumulators; f32x2 packed math; 2 nodes/thread;
// re-zeroes g_aggh for the next replay.
// ---------------------------------------------------------------------------
__global__ void __launch_bounds__(256)
final_kernel(const float* __restrict__ x,
             const float* __restrict__ b_proj, float* __restrict__ out) {
    __shared__ u64 sB0[64], sB1[64], sB2[64], sC[64];
    __shared__ u64 sA0[64], sA1[64], sA2[64], sD[64], sWP[64];

    int pidx = blockIdx.x * blockDim.x + threadIdx.x;  // pre-wait: pure ALU
    int n0 = pidx * 2;
    bool valid = pidx < N_NODES / 2;

    GDC_WAIT();  // scatter's reds + g_w tables (and pack, transitively)

    // Issue node loads first — latency hides under table staging.
    // 2 nodes = 6 consecutive floats at x + 6*pidx (8B aligned: 24*pidx bytes)
    uint2 hA, hB;
    float2 f0, f1, f2;
    if (valid) {
        hA = g_aggh[n0]; hB = g_aggh[n0 + 1];
        const float2* xv = (const float2*)(x + 6 * pidx);
        f0 = __ldg(&xv[0]); f1 = __ldg(&xv[1]); f2 = __ldg(&xv[2]);
    }

    if (threadIdx.x < 64) {
        int p = threadIdx.x;
        float4 u0 = g_w1[2 * p], u1 = g_w1[2 * p + 1];
        sB0[p] = pk(u0.x, u1.x); sB1[p] = pk(u0.y, u1.y);
        sB2[p] = pk(u0.z, u1.z); sC[p]  = pk(u0.w, u1.w);
        float4 v0 = g_w2[2 * p], v1 = g_w2[2 * p + 1];
        sA0[p] = pk(v0.x, v1.x); sA1[p] = pk(v0.y, v1.y);
        sA2[p] = pk(v0.z, v1.z); sD[p]  = pk(v0.w, v1.w);
        sWP[p] = pk(g_wp[2 * p], g_wp[2 * p + 1]);
    }
    __syncthreads();

    if (!valid) return;

    // restore the zero-invariant for the next call (exclusive ownership)
    g_aggh[n0]     = make_uint2(0u, 0u);
    g_aggh[n0 + 1] = make_uint2(0u, 0u);

    // unpack fp16x2 accumulators to f32
    float2 a01A = __half22float2(*(__half2*)&hA.x);
    float2 a2dA = __half22float2(*(__half2*)&hA.y);
    float2 a01B = __half22float2(*(__half2*)&hB.x);
    float2 a2dB = __half22float2(*(__half2*)&hB.y);

    u64 axA = pk1(a01A.x), ayA = pk1(a01A.y), azA = pk1(a2dA.x), awA = pk1(a2dA.y);
    u64 xxA = pk1(f0.x),   xyA = pk1(f0.y),   xzA = pk1(f1.x);
    u64 axB = pk1(a01B.x), ayB = pk1(a01B.y), azB = pk1(a2dB.x), awB = pk1(a2dB.y);
    u64 xxB = pk1(f1.y),   xyB = pk1(f2.x),   xzB = pk1(f2.y);

    u64 accA = pk(0.f, 0.f), accB = pk(0.f, 0.f);

#pragma unroll 8
    for (int p = 0; p < 64; p++) {
        u64 B0 = sB0[p], B1 = sB1[p], B2 = sB2[p], C = sC[p];
        u64 A0 = sA0[p], A1 = sA1[p], A2 = sA2[p], D = sD[p];
        u64 WP = sWP[p];

        u64 pA = D, pB = D;
        FMA2(pA, axA, B0, pA); FMA2(pB, axB, B0, pB);
        FMA2(pA, ayA, B1, pA); FMA2(pB, ayB, B1, pB);
        FMA2(pA, azA, B2, pA); FMA2(pB, azB, B2, pB);
        FMA2(pA, awA, C,  pA); FMA2(pB, awB, C,  pB);
        FMA2(pA, xxA, A0, pA); FMA2(pB, xxB, A0, pB);
        FMA2(pA, xyA, A1, pA); FMA2(pB, xyB, A1, pB);
        FMA2(pA, xzA, A2, pA); FMA2(pB, xzB, A2, pB);

        float a0, a1, b0, b1;
        UNPK(a0, a1, pA); UNPK(b0, b1, pB);
        float t0, t1, t2, t3;
        asm("tanh.approx.f32 %0, %1;" : "=f"(t0) : "f"(a0));
        asm("tanh.approx.f32 %0, %1;" : "=f"(t1) : "f"(a1));
        asm("tanh.approx.f32 %0, %1;" : "=f"(t2) : "f"(b0));
        asm("tanh.approx.f32 %0, %1;" : "=f"(t3) : "f"(b1));
        u64 tA = pk(t0, t1), tB = pk(t2, t3);
        FMA2(accA, tA, WP, accA);
        FMA2(accB, tB, WP, accB);
    }

    float rA0, rA1, rB0, rB1;
    UNPK(rA0, rA1, accA); UNPK(rB0, rB1, accB);
    float bp = b_proj[0];
    out[n0]     = rA0 + rA1 + bp;
    out[n0 + 1] = rB0 + rB1 + bp;
}

// ---------------------------------------------------------------------------
// Launch — inputs: 0:x 1:edge_index(int32) 2:W_lift 3:b_lift 4:W_rel 5:b_rel
//                  6:W_root 7:W_proj 8:b_proj
// PDL: scatter overlaps pack's tail; final overlaps scatter's tail.
// ---------------------------------------------------------------------------
extern "C" void kernel_launch(void* const* d_in, const int* in_sizes, int n_in,
                              void* d_out, int out_size) {
    const float* x      = (const float*)d_in[0];
    const int*   ei     = (const int*)d_in[1];
    const float* W_lift = (const float*)d_in[2];
    const float* b_lift = (const float*)d_in[3];
    const float* W_rel  = (const float*)d_in[4];
    const float* b_rel  = (const float*)d_in[5];
    const float* W_root = (const float*)d_in[6];
    const float* W_proj = (const float*)d_in[7];
    const float* b_proj = (const float*)d_in[8];
    float* out = (float*)d_out;

    pack_kernel<<<(N_NODES + 255) / 256, 256>>>(x);

    cudaLaunchAttribute pdl[1];
    pdl[0].id = cudaLaunchAttributeProgrammaticStreamSerialization;
    pdl[0].val.programmaticStreamSerializationAllowed = 1;

    {
        cudaLaunchConfig_t cfg = {};
        cfg.gridDim  = dim3(1 + (N_EDGES / 8 + 255) / 256);
        cfg.blockDim = dim3(256);
        cfg.attrs = pdl;
        cfg.numAttrs = 1;
        cudaLaunchKernelEx(&cfg, scatter_kernel,
                           ei, W_lift, b_lift, W_rel, b_rel, W_root, W_proj);
    }
    {
        cudaLaunchConfig_t cfg = {};
        cfg.gridDim  = dim3((N_NODES / 2 + 255) / 256);
        cfg.blockDim = dim3(256);
        cfg.attrs = pdl;
        cfg.numAttrs = 1;
        cudaLaunchKernelEx(&cfg, final_kernel, x, b_proj, out);
    }
}

// round 16
// speedup vs baseline: 1.0212x; 1.0212x over previous
#include <cuda_runtime.h>
#include <cuda_fp16.h>

#define N_NODES 100000
#define N_EDGES 1600000
#define HID 128
#define NQUAD (N_EDGES / 4)        // 400000 edge quads
#define SBLK 1184                  // 8 CTAs/SM * 148 SMs = one full wave
#define QSTRIDE ((SBLK - 1) * 256) // 302848 threads doing quads

typedef unsigned long long u64;

// Scratch (__device__ globals per allocation rules; zero-initialized at load).
// INVARIANT: g_aggh is all-zero at every kernel_launch entry — statically
// zeroed before the first call, and final_kernel re-zeroes it after reading
// on every call (each thread exclusively owns its 2 nodes).
__device__ uint2  g_xh[N_NODES];   // {f16x2(x0,x1), f16x2(x2,1)} — scatter src
__device__ uint2  g_aggh[N_NODES]; // fp16x2 accumulators {sum01, sum2_deg}
__device__ float4 g_w1[HID];       // (B0,B1,B2,C): B = W_lift@W_rel, C = b_lift@W_rel
__device__ float4 g_w2[HID];       // (A0,A1,A2,D): A = W_lift@W_root, D = b_lift@W_root + b_rel
__device__ float  g_wp[HID];       // W_proj

__device__ __forceinline__ u64 pk(float lo, float hi) {
    u64 r; asm("mov.b64 %0, {%1, %2};" : "=l"(r) : "f"(lo), "f"(hi)); return r;
}
__device__ __forceinline__ u64 pk1(float v) { return pk(v, v); }
#define FMA2(d, a, b, c) asm("fma.rn.f32x2 %0, %1, %2, %3;" : "=l"(d) : "l"(a), "l"(b), "l"(c))
#define UNPK(lo, hi, v)  asm("mov.b64 {%0, %1}, %2;" : "=f"(lo), "=f"(hi) : "l"(v))
#define REDH(ap, u) \
    asm volatile("red.global.add.noftz.v2.f16x2 [%0], {%1,%2};" \
                 :: "l"(ap), "r"((u).x), "r"((u).y) : "memory")
#define GDC_WAIT() asm volatile("griddepcontrol.wait;" ::: "memory")

// ---------------------------------------------------------------------------
// Kernel 1: pack x into f16x2 pairs for the scatter (800KB total)
// ---------------------------------------------------------------------------
__global__ void pack_kernel(const float* __restrict__ x) {
    int n = blockIdx.x * blockDim.x + threadIdx.x;
    if (n >= N_NODES) return;
    float x0 = x[3 * n], x1 = x[3 * n + 1], x2 = x[3 * n + 2];
    __half2 h01 = __floats2half2_rn(x0, x1);
    __half2 h21 = __floats2half2_rn(x2, 1.0f);
    g_xh[n] = make_uint2(*(unsigned*)&h01, *(unsigned*)&h21);
}

// ---------------------------------------------------------------------------
// Kernel 2 (PDL secondary of pack), exactly ONE wave (1184 blocks):
//   block 0  = weight fold — no dependency on pack, runs entirely pre-wait
//   blocks 1..1183 = fp16x2 scatter-add, grid-stride over edge quads
//                    (<=2 quads/thread; perfectly balanced, no wave-2)
// ---------------------------------------------------------------------------
__global__ void __launch_bounds__(256)
scatter_kernel(const int* __restrict__ ei,
               const float* __restrict__ W_lift,
               const float* __restrict__ b_lift,
               const float* __restrict__ W_rel,
               const float* __restrict__ b_rel,
               const float* __restrict__ W_root,
               const float* __restrict__ W_proj) {
    if (blockIdx.x == 0) {
        // ---- weight fold: reads only kernel args (independent of pack) ----
        __shared__ float red[2][8][HID];  // 8KB
        int f = threadIdx.x & 127;
        int g = threadIdx.x >> 7;  // 0 or 1
        float b0 = 0.f, b1 = 0.f, b2 = 0.f, c = 0.f;
        float a0 = 0.f, a1 = 0.f, a2 = 0.f, d = 0.f;
        int k0 = g * 64;
#pragma unroll 16
        for (int i = 0; i < 64; i++) {
            int k = k0 + i;
            float wr = W_rel[k * HID + f];
            float wo = W_root[k * HID + f];
            float l0 = W_lift[0 * HID + k];
            float l1 = W_lift[1 * HID + k];
            float l2 = W_lift[2 * HID + k];
            float bl = b_lift[k];
            b0 += l0 * wr; b1 += l1 * wr; b2 += l2 * wr; c += bl * wr;
            a0 += l0 * wo; a1 += l1 * wo; a2 += l2 * wo; d += bl * wo;
        }
        red[g][0][f] = b0; red[g][1][f] = b1; red[g][2][f] = b2; red[g][3][f] = c;
        red[g][4][f] = a0; red[g][5][f] = a1; red[g][6][f] = a2; red[g][7][f] = d;
        __syncthreads();
        if (g == 0) {
            float s[8];
#pragma unroll
            for (int ch = 0; ch < 8; ch++) s[ch] = red[0][ch][f] + red[1][ch][f];
            g_w1[f] = make_float4(s[0], s[1], s[2], s[3]);
            g_w2[f] = make_float4(s[4], s[5], s[6], s[7] + b_rel[f]);
            g_wp[f] = W_proj[f];
        }
        return;
    }

    // ---- scatter: grid-stride over quads (4 edges each), fp16x2 payload ----
    int q = (blockIdx.x - 1) * 256 + threadIdx.x;
    bool have = q < NQUAD;
    int4 s4, d4;
    if (have) {                         // pre-wait: harness input
        s4 = *(const int4*)(ei + 4 * q);
        d4 = *(const int4*)(ei + N_EDGES + 4 * q);
    }

    GDC_WAIT();  // pack's g_xh writes must be visible past this point

    while (have) {
        // all 4 gathers in flight before any red
        uint2 v0 = __ldg(&g_xh[(unsigned)s4.x]);
        uint2 v1 = __ldg(&g_xh[(unsigned)s4.y]);
        uint2 v2 = __ldg(&g_xh[(unsigned)s4.z]);
        uint2 v3 = __ldg(&g_xh[(unsigned)s4.w]);

        uint2* a0 = &g_aggh[(unsigned)d4.x];
        uint2* a1 = &g_aggh[(unsigned)d4.y];
        uint2* a2 = &g_aggh[(unsigned)d4.z];
        uint2* a3 = &g_aggh[(unsigned)d4.w];

        q += QSTRIDE;
        have = q < NQUAD;
        int4 ns4, nd4;
        if (have) {                     // prefetch next quad's indices
            ns4 = *(const int4*)(ei + 4 * q);
            nd4 = *(const int4*)(ei + N_EDGES + 4 * q);
        }

        REDH(a0, v0);
        REDH(a1, v1);
        REDH(a2, v2);
        REDH(a3, v3);

        s4 = ns4; d4 = nd4;
    }
}

// ---------------------------------------------------------------------------
// Kernel 3 (PDL secondary of scatter):
//   out[n] = sum_f tanh(dot(agg,w1_f)+dot(x,1,w2_f)) * wp_f + b_proj
// Root-term x read DIRECTLY from the input (coalesced float2 loads).
// agg read from fp16x2 accumulators; f32x2 packed math; 2 nodes/thread;
// re-zeroes g_aggh for the next replay.
// ---------------------------------------------------------------------------
__global__ void __launch_bounds__(256)
final_kernel(const float* __restrict__ x,
             const float* __restrict__ b_proj, float* __restrict__ out) {
    __shared__ u64 sB0[64], sB1[64], sB2[64], sC[64];
    __shared__ u64 sA0[64], sA1[64], sA2[64], sD[64], sWP[64];

    int pidx = blockIdx.x * blockDim.x + threadIdx.x;  // pre-wait: pure ALU
    int n0 = pidx * 2;
    bool valid = pidx < N_NODES / 2;

    GDC_WAIT();  // scatter's reds + g_w tables (and pack, transitively)

    // Issue node loads first — latency hides under table staging.
    uint2 hA, hB;
    float2 f0, f1, f2;
    if (valid) {
        hA = g_aggh[n0]; hB = g_aggh[n0 + 1];
        const float2* xv = (const float2*)(x + 6 * pidx);
        f0 = __ldg(&xv[0]); f1 = __ldg(&xv[1]); f2 = __ldg(&xv[2]);
    }

    if (threadIdx.x < 64) {
        int p = threadIdx.x;
        float4 u0 = g_w1[2 * p], u1 = g_w1[2 * p + 1];
        sB0[p] = pk(u0.x, u1.x); sB1[p] = pk(u0.y, u1.y);
        sB2[p] = pk(u0.z, u1.z); sC[p]  = pk(u0.w, u1.w);
        float4 v0 = g_w2[2 * p], v1 = g_w2[2 * p + 1];
        sA0[p] = pk(v0.x, v1.x); sA1[p] = pk(v0.y, v1.y);
        sA2[p] = pk(v0.z, v1.z); sD[p]  = pk(v0.w, v1.w);
        sWP[p] = pk(g_wp[2 * p], g_wp[2 * p + 1]);
    }
    __syncthreads();

    if (!valid) return;

    // restore the zero-invariant for the next call (exclusive ownership)
    g_aggh[n0]     = make_uint2(0u, 0u);
    g_aggh[n0 + 1] = make_uint2(0u, 0u);

    // unpack fp16x2 accumulators to f32
    float2 a01A = __half22float2(*(__half2*)&hA.x);
    float2 a2dA = __half22float2(*(__half2*)&hA.y);
    float2 a01B = __half22float2(*(__half2*)&hB.x);
    float2 a2dB = __half22float2(*(__half2*)&hB.y);

    u64 axA = pk1(a01A.x), ayA = pk1(a01A.y), azA = pk1(a2dA.x), awA = pk1(a2dA.y);
    u64 xxA = pk1(f0.x),   xyA = pk1(f0.y),   xzA = pk1(f1.x);
    u64 axB = pk1(a01B.x), ayB = pk1(a01B.y), azB = pk1(a2dB.x), awB = pk1(a2dB.y);
    u64 xxB = pk1(f1.y),   xyB = pk1(f2.x),   xzB = pk1(f2.y);

    u64 accA = pk(0.f, 0.f), accB = pk(0.f, 0.f);

#pragma unroll 8
    for (int p = 0; p < 64; p++) {
        u64 B0 = sB0[p], B1 = sB1[p], B2 = sB2[p], C = sC[p];
        u64 A0 = sA0[p], A1 = sA1[p], A2 = sA2[p], D = sD[p];
        u64 WP = sWP[p];

        u64 pA = D, pB = D;
        FMA2(pA, axA, B0, pA); FMA2(pB, axB, B0, pB);
        FMA2(pA, ayA, B1, pA); FMA2(pB, ayB, B1, pB);
        FMA2(pA, azA, B2, pA); FMA2(pB, azB, B2, pB);
        FMA2(pA, awA, C,  pA); FMA2(pB, awB, C,  pB);
        FMA2(pA, xxA, A0, pA); FMA2(pB, xxB, A0, pB);
        FMA2(pA, xyA, A1, pA); FMA2(pB, xyB, A1, pB);
        FMA2(pA, xzA, A2, pA); FMA2(pB, xzB, A2, pB);

        float a0, a1, b0, b1;
        UNPK(a0, a1, pA); UNPK(b0, b1, pB);
        float t0, t1, t2, t3;
        asm("tanh.approx.f32 %0, %1;" : "=f"(t0) : "f"(a0));
        asm("tanh.approx.f32 %0, %1;" : "=f"(t1) : "f"(a1));
        asm("tanh.approx.f32 %0, %1;" : "=f"(t2) : "f"(b0));
        asm("tanh.approx.f32 %0, %1;" : "=f"(t3) : "f"(b1));
        u64 tA = pk(t0, t1), tB = pk(t2, t3);
        FMA2(accA, tA, WP, accA);
        FMA2(accB, tB, WP, accB);
    }

    float rA0, rA1, rB0, rB1;
    UNPK(rA0, rA1, accA); UNPK(rB0, rB1, accB);
    float bp = b_proj[0];
    out[n0]     = rA0 + rA1 + bp;
    out[n0 + 1] = rB0 + rB1 + bp;
}

// ---------------------------------------------------------------------------
// Launch — inputs: 0:x 1:edge_index(int32) 2:W_lift 3:b_lift 4:W_rel 5:b_rel
//                  6:W_root 7:W_proj 8:b_proj
// PDL: scatter overlaps pack's tail; final overlaps scatter's tail.
// ---------------------------------------------------------------------------
extern "C" void kernel_launch(void* const* d_in, const int* in_sizes, int n_in,
                              void* d_out, int out_size) {
    const float* x      = (const float*)d_in[0];
    const int*   ei     = (const int*)d_in[1];
    const float* W_lift = (const float*)d_in[2];
    const float* b_lift = (const float*)d_in[3];
    const float* W_rel  = (const float*)d_in[4];
    const float* b_rel  = (const float*)d_in[5];
    const float* W_root = (const float*)d_in[6];
    const float* W_proj = (const float*)d_in[7];
    const float* b_proj = (const float*)d_in[8];
    float* out = (float*)d_out;

    pack_kernel<<<(N_NODES + 255) / 256, 256>>>(x);

    cudaLaunchAttribute pdl[1];
    pdl[0].id = cudaLaunchAttributeProgrammaticStreamSerialization;
    pdl[0].val.programmaticStreamSerializationAllowed = 1;

    {
        cudaLaunchConfig_t cfg = {};
        cfg.gridDim  = dim3(SBLK);
        cfg.blockDim = dim3(256);
        cfg.attrs = pdl;
        cfg.numAttrs = 1;
        cudaLaunchKernelEx(&cfg, scatter_kernel,
                           ei, W_lift, b_lift, W_rel, b_rel, W_root, W_proj);
    }
    {
        cudaLaunchConfig_t cfg = {};
        cfg.gridDim  = dim3((N_NODES / 2 + 255) / 256);
        cfg.blockDim = dim3(256);
        cfg.attrs = pdl;
        cfg.numAttrs = 1;
        cudaLaunchKernelEx(&cfg, final_kernel, x, b_proj, out);
    }
}

// round 17
// speedup vs baseline: 1.2363x; 1.2107x over previous
#include <cuda_runtime.h>
#include <cuda_fp16.h>

#define N_NODES 100000
#define N_EDGES 1600000
#define HID 128
#define NQUAD (N_EDGES / 4)        // 400000 edge quads
#define SBLK 592                   // 4 CTAs/SM * 148 SMs = one full wave @512t
#define STHR 512
#define QSTRIDE ((SBLK - 1) * STHR) // 302592 threads doing quads

typedef unsigned long long u64;

// Scratch (__device__ globals per allocation rules; zero-initialized at load).
// INVARIANT: g_aggh is all-zero at every kernel_launch entry — statically
// zeroed before the first call, and final_kernel re-zeroes it after reading
// on every call (each thread exclusively owns its 2 nodes).
__device__ uint2  g_xh[N_NODES];   // {f16x2(x0,x1), f16x2(x2,1)} — scatter src
__device__ uint2  g_aggh[N_NODES]; // fp16x2 accumulators {sum01, sum2_deg}
__device__ float4 g_w1[HID];       // (B0,B1,B2,C): B = W_lift@W_rel, C = b_lift@W_rel
__device__ float4 g_w2[HID];       // (A0,A1,A2,D): A = W_lift@W_root, D = b_lift@W_root + b_rel
__device__ float  g_wp[HID];       // W_proj

__device__ __forceinline__ u64 pk(float lo, float hi) {
    u64 r; asm("mov.b64 %0, {%1, %2};" : "=l"(r) : "f"(lo), "f"(hi)); return r;
}
__device__ __forceinline__ u64 pk1(float v) { return pk(v, v); }
#define FMA2(d, a, b, c) asm("fma.rn.f32x2 %0, %1, %2, %3;" : "=l"(d) : "l"(a), "l"(b), "l"(c))
#define UNPK(lo, hi, v)  asm("mov.b64 {%0, %1}, %2;" : "=f"(lo), "=f"(hi) : "l"(v))
#define REDH(ap, u) \
    asm volatile("red.global.add.noftz.v2.f16x2 [%0], {%1,%2};" \
                 :: "l"(ap), "r"((u).x), "r"((u).y) : "memory")
#define GDC_WAIT() asm volatile("griddepcontrol.wait;" ::: "memory")

// ---------------------------------------------------------------------------
// Kernel 1: pack x into f16x2 pairs for the scatter (800KB total)
// ---------------------------------------------------------------------------
__global__ void pack_kernel(const float* __restrict__ x) {
    int n = blockIdx.x * blockDim.x + threadIdx.x;
    if (n >= N_NODES) return;
    float x0 = x[3 * n], x1 = x[3 * n + 1], x2 = x[3 * n + 2];
    __half2 h01 = __floats2half2_rn(x0, x1);
    __half2 h21 = __floats2half2_rn(x2, 1.0f);
    g_xh[n] = make_uint2(*(unsigned*)&h01, *(unsigned*)&h21);
}

// ---------------------------------------------------------------------------
// Kernel 2 (PDL secondary of pack), exactly ONE wave (592 x 512):
//   block 0  = weight fold (k split 4 ways, 32 serial k's) — pack-independent
//   blocks 1..591 = fp16x2 scatter-add, grid-stride over edge quads
// ---------------------------------------------------------------------------
__global__ void __launch_bounds__(STHR)
scatter_kernel(const int* __restrict__ ei,
               const float* __restrict__ W_lift,
               const float* __restrict__ b_lift,
               const float* __restrict__ W_rel,
               const float* __restrict__ b_rel,
               const float* __restrict__ W_root,
               const float* __restrict__ W_proj) {
    if (blockIdx.x == 0) {
        // ---- weight fold: f = tid&127, k split 4 ways (32 serial each) ----
        __shared__ float red[4][8][HID];  // 16KB
        int f = threadIdx.x & 127;
        int g = threadIdx.x >> 7;  // 0..3
        float b0 = 0.f, b1 = 0.f, b2 = 0.f, c = 0.f;
        float a0 = 0.f, a1 = 0.f, a2 = 0.f, d = 0.f;
        int k0 = g * 32;
#pragma unroll
        for (int i = 0; i < 32; i++) {
            int k = k0 + i;
            float wr = W_rel[k * HID + f];
            float wo = W_root[k * HID + f];
            float l0 = W_lift[0 * HID + k];
            float l1 = W_lift[1 * HID + k];
            float l2 = W_lift[2 * HID + k];
            float bl = b_lift[k];
            b0 += l0 * wr; b1 += l1 * wr; b2 += l2 * wr; c += bl * wr;
            a0 += l0 * wo; a1 += l1 * wo; a2 += l2 * wo; d += bl * wo;
        }
        red[g][0][f] = b0; red[g][1][f] = b1; red[g][2][f] = b2; red[g][3][f] = c;
        red[g][4][f] = a0; red[g][5][f] = a1; red[g][6][f] = a2; red[g][7][f] = d;
        __syncthreads();
        if (g == 0) {
            float s[8];
#pragma unroll
            for (int ch = 0; ch < 8; ch++)
                s[ch] = (red[0][ch][f] + red[1][ch][f]) + (red[2][ch][f] + red[3][ch][f]);
            g_w1[f] = make_float4(s[0], s[1], s[2], s[3]);
            g_w2[f] = make_float4(s[4], s[5], s[6], s[7] + b_rel[f]);
            g_wp[f] = W_proj[f];
        }
        return;
    }

    // ---- scatter: grid-stride over quads (4 edges each), fp16x2 payload ----
    int q = (blockIdx.x - 1) * STHR + threadIdx.x;
    bool have = q < NQUAD;
    int4 s4, d4;
    if (have) {                         // pre-wait: harness input
        s4 = *(const int4*)(ei + 4 * q);
        d4 = *(const int4*)(ei + N_EDGES + 4 * q);
    }

    GDC_WAIT();  // pack's g_xh writes must be visible past this point

    while (have) {
        // all 4 gathers in flight before any red
        uint2 v0 = __ldg(&g_xh[(unsigned)s4.x]);
        uint2 v1 = __ldg(&g_xh[(unsigned)s4.y]);
        uint2 v2 = __ldg(&g_xh[(unsigned)s4.z]);
        uint2 v3 = __ldg(&g_xh[(unsigned)s4.w]);

        uint2* a0 = &g_aggh[(unsigned)d4.x];
        uint2* a1 = &g_aggh[(unsigned)d4.y];
        uint2* a2 = &g_aggh[(unsigned)d4.z];
        uint2* a3 = &g_aggh[(unsigned)d4.w];

        q += QSTRIDE;
        have = q < NQUAD;
        int4 ns4, nd4;
        if (have) {                     // prefetch next quad's indices
            ns4 = *(const int4*)(ei + 4 * q);
            nd4 = *(const int4*)(ei + N_EDGES + 4 * q);
        }

        REDH(a0, v0);
        REDH(a1, v1);
        REDH(a2, v2);
        REDH(a3, v3);

        s4 = ns4; d4 = nd4;
    }
}

// ---------------------------------------------------------------------------
// Kernel 3 (PDL secondary of scatter):
//   out[n] = sum_f tanh(dot(agg,w1_f)+dot(x,1,w2_f)) * wp_f + b_proj
// Root-term x read DIRECTLY from the input (coalesced float2 loads).
// agg read from fp16x2 accumulators; f32x2 packed math; 2 nodes/thread;
// re-zeroes g_aggh for the next replay.
// ---------------------------------------------------------------------------
__global__ void __launch_bounds__(256)
final_kernel(const float* __restrict__ x,
             const float* __restrict__ b_proj, float* __restrict__ out) {
    __shared__ u64 sB0[64], sB1[64], sB2[64], sC[64];
    __shared__ u64 sA0[64], sA1[64], sA2[64], sD[64], sWP[64];

    int pidx = blockIdx.x * blockDim.x + threadIdx.x;  // pre-wait: pure ALU
    int n0 = pidx * 2;
    bool valid = pidx < N_NODES / 2;

    GDC_WAIT();  // scatter's reds + g_w tables (and pack, transitively)

    // Issue node loads first — latency hides under table staging.
    uint2 hA, hB;
    float2 f0, f1, f2;
    if (valid) {
        hA = g_aggh[n0]; hB = g_aggh[n0 + 1];
        const float2* xv = (const float2*)(x + 6 * pidx);
        f0 = __ldg(&xv[0]); f1 = __ldg(&xv[1]); f2 = __ldg(&xv[2]);
    }

    if (threadIdx.x < 64) {
        int p = threadIdx.x;
        float4 u0 = g_w1[2 * p], u1 = g_w1[2 * p + 1];
        sB0[p] = pk(u0.x, u1.x); sB1[p] = pk(u0.y, u1.y);
        sB2[p] = pk(u0.z, u1.z); sC[p]  = pk(u0.w, u1.w);
        float4 v0 = g_w2[2 * p], v1 = g_w2[2 * p + 1];
        sA0[p] = pk(v0.x, v1.x); sA1[p] = pk(v0.y, v1.y);
        sA2[p] = pk(v0.z, v1.z); sD[p]  = pk(v0.w, v1.w);
        sWP[p] = pk(g_wp[2 * p], g_wp[2 * p + 1]);
    }
    __syncthreads();

    if (!valid) return;

    // restore the zero-invariant for the next call (exclusive ownership)
    g_aggh[n0]     = make_uint2(0u, 0u);
    g_aggh[n0 + 1] = make_uint2(0u, 0u);

    // unpack fp16x2 accumulators to f32
    float2 a01A = __half22float2(*(__half2*)&hA.x);
    float2 a2dA = __half22float2(*(__half2*)&hA.y);
    float2 a01B = __half22float2(*(__half2*)&hB.x);
    float2 a2dB = __half22float2(*(__half2*)&hB.y);

    u64 axA = pk1(a01A.x), ayA = pk1(a01A.y), azA = pk1(a2dA.x), awA = pk1(a2dA.y);
    u64 xxA = pk1(f0.x),   xyA = pk1(f0.y),   xzA = pk1(f1.x);
    u64 axB = pk1(a01B.x), ayB = pk1(a01B.y), azB = pk1(a2dB.x), awB = pk1(a2dB.y);
    u64 xxB = pk1(f1.y),   xyB = pk1(f2.x),   xzB = pk1(f2.y);

    u64 accA = pk(0.f, 0.f), accB = pk(0.f, 0.f);

#pragma unroll 8
    for (int p = 0; p < 64; p++) {
        u64 B0 = sB0[p], B1 = sB1[p], B2 = sB2[p], C = sC[p];
        u64 A0 = sA0[p], A1 = sA1[p], A2 = sA2[p], D = sD[p];
        u64 WP = sWP[p];

        u64 pA = D, pB = D;
        FMA2(pA, axA, B0, pA); FMA2(pB, axB, B0, pB);
        FMA2(pA, ayA, B1, pA); FMA2(pB, ayB, B1, pB);
        FMA2(pA, azA, B2, pA); FMA2(pB, azB, B2, pB);
        FMA2(pA, awA, C,  pA); FMA2(pB, awB, C,  pB);
        FMA2(pA, xxA, A0, pA); FMA2(pB, xxB, A0, pB);
        FMA2(pA, xyA, A1, pA); FMA2(pB, xyB, A1, pB);
        FMA2(pA, xzA, A2, pA); FMA2(pB, xzB, A2, pB);

        float a0, a1, b0, b1;
        UNPK(a0, a1, pA); UNPK(b0, b1, pB);
        float t0, t1, t2, t3;
        asm("tanh.approx.f32 %0, %1;" : "=f"(t0) : "f"(a0));
        asm("tanh.approx.f32 %0, %1;" : "=f"(t1) : "f"(a1));
        asm("tanh.approx.f32 %0, %1;" : "=f"(t2) : "f"(b0));
        asm("tanh.approx.f32 %0, %1;" : "=f"(t3) : "f"(b1));
        u64 tA = pk(t0, t1), tB = pk(t2, t3);
        FMA2(accA, tA, WP, accA);
        FMA2(accB, tB, WP, accB);
    }

    float rA0, rA1, rB0, rB1;
    UNPK(rA0, rA1, accA); UNPK(rB0, rB1, accB);
    float bp = b_proj[0];
    out[n0]     = rA0 + rA1 + bp;
    out[n0 + 1] = rB0 + rB1 + bp;
}

// ---------------------------------------------------------------------------
// Launch — inputs: 0:x 1:edge_index(int32) 2:W_lift 3:b_lift 4:W_rel 5:b_rel
//                  6:W_root 7:W_proj 8:b_proj
// PDL: scatter overlaps pack's tail; final overlaps scatter's tail.
// ---------------------------------------------------------------------------
extern "C" void kernel_launch(void* const* d_in, const int* in_sizes, int n_in,
                              void* d_out, int out_size) {
    const float* x      = (const float*)d_in[0];
    const int*   ei     = (const int*)d_in[1];
    const float* W_lift = (const float*)d_in[2];
    const float* b_lift = (const float*)d_in[3];
    const float* W_rel  = (const float*)d_in[4];
    const float* b_rel  = (const float*)d_in[5];
    const float* W_root = (const float*)d_in[6];
    const float* W_proj = (const float*)d_in[7];
    const float* b_proj = (const float*)d_in[8];
    float* out = (float*)d_out;

    pack_kernel<<<(N_NODES + 255) / 256, 256>>>(x);

    cudaLaunchAttribute pdl[1];
    pdl[0].id = cudaLaunchAttributeProgrammaticStreamSerialization;
    pdl[0].val.programmaticStreamSerializationAllowed = 1;

    {
        cudaLaunchConfig_t cfg = {};
        cfg.gridDim  = dim3(SBLK);
        cfg.blockDim = dim3(STHR);
        cfg.attrs = pdl;
        cfg.numAttrs = 1;
        cudaLaunchKernelEx(&cfg, scatter_kernel,
                           ei, W_lift, b_lift, W_rel, b_rel, W_root, W_proj);
    }
    {
        cudaLaunchConfig_t cfg = {};
        cfg.gridDim  = dim3((N_NODES / 2 + 255) / 256);
        cfg.blockDim = dim3(256);
        cfg.attrs = pdl;
        cfg.numAttrs = 1;
        cudaLaunchKernelEx(&cfg, final_kernel, x, b_proj, out);
    }
}